// round 9
// baseline (speedup 1.0000x reference)
#include <cuda_runtime.h>
#include <math.h>

#define NB    8
#define NC    64
#define NPIX  1600
#define TOPK  10
#define TKPAD 12
#define NNZ   (NPIX * TOPK)
#define SORTN 2048
#define FULLW 0xFFFFFFFFu

// ---------------- static scratch (no runtime allocation) ----------------
__device__ float g_xx  [NB * NPIX];        // relu conv logits (pre-softmax)
__device__ int   g_topk[NB * NPIX * TKPAD];
__device__ float g_dv2 [NB * NPIX];
__device__ int   g_off [NB * (NPIX + 1)];
__device__ int   g_ecol[NB * NNZ];
__device__ float g_Z   [NB * NPIX * NC];   // 0.1*dv2-scaled features (X@W + b)
__device__ float g_Y   [NB * NPIX * NC];   // per-hyperedge features
__device__ float g_Hf  [NB * NPIX * NC];   // vertex output of a layer

__device__ __forceinline__ float4 f4add(float4 a, float4 b) {
    a.x += b.x; a.y += b.y; a.z += b.z; a.w += b.w; return a;
}
__device__ __forceinline__ unsigned long long u64min_(unsigned long long a, unsigned long long b) { return a < b ? a : b; }
__device__ __forceinline__ unsigned long long u64max_(unsigned long long a, unsigned long long b) { return a > b ? a : b; }

// ---------------- K1: 1x1 conv + relu, wide grid (logits only)
__global__ void k_convA(const float* __restrict__ x,
                        const float* __restrict__ w,
                        const float* __restrict__ bconst)
{
    int b = blockIdx.y, t = threadIdx.x;
    __shared__ float ws[NC];
    if (t < NC) ws[t] = w[t];
    __syncthreads();
    int p = blockIdx.x * 256 + t;
    if (p >= NPIX) return;
    const float* xb = x + (size_t)b * NC * NPIX;
    float acc = bconst[0];
    #pragma unroll
    for (int c = 0; c < NC; c++) acc += xb[c*NPIX + p] * ws[c];
    g_xx[b*NPIX + p] = fmaxf(acc, 0.f);
}

// ---------------- K2: softmax + full graph build per batch.
__global__ __launch_bounds__(1024) void k_build(float* __restrict__ outz)
{
    int b = blockIdx.x, t = threadIdx.x;
    int lane = t & 31, wid = t >> 5;
    __shared__ unsigned long long skey[SORTN];      // 16 KB
    __shared__ unsigned short rs[NPIX], re[NPIX];   // run start/end per sorted pos
    __shared__ unsigned short pos[NPIX];            // original idx -> sorted pos
    __shared__ int dv[NPIX];                        // DV, later reused as fill cursor
    __shared__ int off[NPIX + 1];
    __shared__ int part[1024];                      // scan scratch / float scratch

    if (t == 0) outz[b] = 0.f;                      // zero the output accumulator

    // ---- softmax over relu logits (1600 elems, 1024 threads) ----
    float* rf = (float*)part;
    float v0 = g_xx[b*NPIX + t];
    float v1 = (t + 1024 < NPIX) ? g_xx[b*NPIX + t + 1024] : -3.4e38f;
    rf[t] = fmaxf(v0, v1); __syncthreads();
    for (int s = 512; s > 0; s >>= 1) { if (t < s) rf[t] = fmaxf(rf[t], rf[t+s]); __syncthreads(); }
    float mx = rf[0]; __syncthreads();
    float e0 = expf(v0 - mx);
    float e1 = (t + 1024 < NPIX) ? expf(v1 - mx) : 0.f;
    rf[t] = e0 + e1; __syncthreads();
    for (int s = 512; s > 0; s >>= 1) { if (t < s) rf[t] += rf[t+s]; __syncthreads(); }
    float inv = 1.f / rf[0]; __syncthreads();

    // pack keys in regs: (float bits of xx)<<32 | idx  (xx > 0 => bits monotone)
    unsigned long long a0 = ((unsigned long long)__float_as_uint(e0 * inv) << 32) | (unsigned)t;
    unsigned long long a1 = (t + 1024 < NPIX)
        ? (((unsigned long long)__float_as_uint(e1 * inv) << 32) | (unsigned)(t + 1024))
        : 0xFFFFFFFFFFFFFFFFull;

    // reg-phase: exchange at distance j (<=16, intra-warp) for elements t, t+1024
    #define REGPHASE(KSZ, J) { \
        unsigned long long p0 = __shfl_xor_sync(FULLW, a0, (J)); \
        unsigned long long p1 = __shfl_xor_sync(FULLW, a1, (J)); \
        int i0 = t, i1 = t + 1024; \
        bool m0 = (((i0 & (J)) == 0) == ((i0 & (KSZ)) == 0)); \
        bool m1 = (((i1 & (J)) == 0) == ((i1 & (KSZ)) == 0)); \
        a0 = m0 ? u64min_(a0, p0) : u64max_(a0, p0); \
        a1 = m1 ? u64min_(a1, p1) : u64max_(a1, p1); }

    for (int ksz = 2; ksz <= 32; ksz <<= 1)
        for (int j = ksz >> 1; j >= 1; j >>= 1)
            REGPHASE(ksz, j);
    skey[t] = a0; skey[t + 1024] = a1; __syncthreads();

    for (int ksz = 64; ksz <= SORTN; ksz <<= 1) {
        int jstart = ksz >> 1;
        if (ksz == SORTN) {
            unsigned long long lo = u64min_(a0, a1), hi = u64max_(a0, a1);
            a0 = lo; a1 = hi;
            skey[t] = a0; skey[t + 1024] = a1; __syncthreads();
            jstart = 512;
        }
        for (int j = jstart; j >= 32; j >>= 1) {
            #pragma unroll
            for (int r = 0; r < 2; r++) {
                int i = t + r * 1024;
                int ixj = i ^ j;
                if (ixj > i) {
                    unsigned long long a = skey[i], c = skey[ixj];
                    bool up = ((i & ksz) == 0);
                    if ((a > c) == up) { skey[i] = c; skey[ixj] = a; }
                }
            }
            __syncthreads();
        }
        a0 = skey[t]; a1 = skey[t + 1024];
        for (int j = 16; j >= 1; j >>= 1)
            REGPHASE(ksz, j);
        skey[t] = a0; skey[t + 1024] = a1; __syncthreads();
    }

    // run bounds (equal-value runs) via binary search; pos scatter; DV=0
    for (int p = t; p < NPIX; p += 1024) {
        unsigned v = (unsigned)(skey[p] >> 32);
        int lo = 0, hi = p;
        while (lo < hi) { int m = (lo + hi) >> 1;
            if ((unsigned)(skey[m] >> 32) < v) lo = m + 1; else hi = m; }
        rs[p] = (unsigned short)lo;
        int lo2 = p + 1, hi2 = NPIX;
        while (lo2 < hi2) { int m = (lo2 + hi2) >> 1;
            if ((unsigned)(skey[m] >> 32) <= v) lo2 = m + 1; else hi2 = m; }
        re[p] = (unsigned short)(lo2 - 1);
        pos[(unsigned)(skey[p] & 0xFFFFFFFFu)] = (unsigned short)p;
        dv[p] = 0;
    }
    __syncthreads();

    // per-row top-k walk (exact stable-argsort (d,idx) semantics incl. ties)
    // NPIX=1600: pass0 all 1024 threads, pass1 threads t<576 (576%32==0 -> warp-uniform)
    for (int i = t; i < NPIX; i += 1024) {
        int p = pos[i];
        float vi = __uint_as_float((unsigned)(skey[p] >> 32));
        int out[TOPK]; int cnt = 0;
        int a = rs[p], bnd = re[p];
        for (int q = a; q <= bnd && cnt < TOPK; q++)
            out[cnt++] = (int)(skey[q] & 0xFFFFFFFFu);
        int L = a - 1, R = bnd + 1;
        while (cnt < TOPK) {
            float dL = (L >= 0)   ? vi - __uint_as_float((unsigned)(skey[L] >> 32)) : 3.4e38f;
            float dR = (R < NPIX) ? __uint_as_float((unsigned)(skey[R] >> 32)) - vi : 3.4e38f;
            if (dL < dR) {
                int s2 = rs[L];
                for (int q = s2; q <= L && cnt < TOPK; q++)
                    out[cnt++] = (int)(skey[q] & 0xFFFFFFFFu);
                L = s2 - 1;
            } else if (dR < dL) {
                int e2 = re[R];
                for (int q = R; q <= e2 && cnt < TOPK; q++)
                    out[cnt++] = (int)(skey[q] & 0xFFFFFFFFu);
                R = e2 + 1;
            } else {                                  // exact distance tie: merge by idx
                int sL = rs[L], eR = re[R];
                int qa = sL, qb = R;
                while (cnt < TOPK && (qa <= L || qb <= eR)) {
                    int ia = (qa <= L)  ? (int)(skey[qa] & 0xFFFFFFFFu) : 0x7FFFFFFF;
                    int ib = (qb <= eR) ? (int)(skey[qb] & 0xFFFFFFFFu) : 0x7FFFFFFF;
                    if (ia < ib) { out[cnt++] = ia; qa++; }
                    else         { out[cnt++] = ib; qb++; }
                }
                L = sL - 1; R = eR + 1;
            }
        }
        bool has = false;
        #pragma unroll
        for (int j2 = 0; j2 < TOPK; j2++) has |= (out[j2] == i);
        if (!has) out[TOPK-1] = i;                    // reference self rule

        int base = (b*NPIX + i) * TKPAD;
        #pragma unroll
        for (int j2 = 0; j2 < TOPK; j2++) {
            g_topk[base + j2] = out[j2];
            // warp-aggregated DV increment (hub vertices get ~800 hits otherwise)
            int v = out[j2];
            unsigned m = __match_any_sync(FULLW, v);
            int ldr = __ffs(m) - 1;
            if (lane == ldr) atomicAdd(&dv[v], __popc(m));
        }
    }
    __syncthreads();

    // exclusive scan of DV (pairs) -> offsets; dv2   [shfl 3-level scan, 3 barriers]
    int p0 = t * 2;
    int sv = (p0 < NPIX) ? dv[p0] + dv[p0+1] : 0;
    int incl = sv;
    #pragma unroll
    for (int d2 = 1; d2 < 32; d2 <<= 1) {
        int vv = __shfl_up_sync(FULLW, incl, d2);
        if (lane >= d2) incl += vv;
    }
    if (lane == 31) part[wid] = incl;
    __syncthreads();
    if (wid == 0) {
        int w = part[lane];
        #pragma unroll
        for (int d2 = 1; d2 < 32; d2 <<= 1) {
            int vv = __shfl_up_sync(FULLW, w, d2);
            if (lane >= d2) w += vv;
        }
        part[lane] = w;
    }
    __syncthreads();
    int total_incl = incl + (wid ? part[wid-1] : 0);
    if (p0 < NPIX) {
        int excl = total_incl - sv;
        off[p0] = excl; off[p0+1] = excl + dv[p0];
        g_off[b*(NPIX+1) + p0]     = excl;
        g_off[b*(NPIX+1) + p0 + 1] = excl + dv[p0];
        g_dv2[b*NPIX + p0]     = rsqrtf((float)dv[p0]);
        g_dv2[b*NPIX + p0 + 1] = rsqrtf((float)dv[p0+1]);
    }
    if (t == 0) { off[NPIX] = NNZ; g_off[b*(NPIX+1) + NPIX] = NNZ; }
    __syncthreads();

    // CSR fill (reuse dv as cursor), warp-aggregated cursor bump
    for (int p = t; p < NPIX; p += 1024) dv[p] = 0;
    __syncthreads();
    // NNZ=16000: last pass threads t<640 (640%32==0 -> warp-uniform)
    for (int s2 = t; s2 < NNZ; s2 += 1024) {
        int e = s2 / TOPK, j2 = s2 - e * TOPK;
        int v = g_topk[(b*NPIX + e) * TKPAD + j2];
        unsigned m = __match_any_sync(FULLW, v);
        int ldr = __ffs(m) - 1;
        int rank = __popc(m & ((1u << lane) - 1));
        int basep = 0;
        if (lane == ldr) basep = atomicAdd(&dv[v], __popc(m));
        basep = __shfl_sync(FULLW, basep, ldr);
        g_ecol[b*NNZ + off[v] + basep + rank] = e;
    }
}

// ---------------- K3/K6: Z[v,:] = 0.1*dv2[v] * (X[v,:] @ W + bias)
__global__ void k_gemm(const float* __restrict__ X,
                       const float* __restrict__ W,
                       const float* __restrict__ bias,
                       int useH)
{
    int b  = blockIdx.y;
    int r0 = blockIdx.x * 64;
    __shared__ float As[64 * 64];
    __shared__ float Ws[64 * 64];
    int t = threadIdx.x;
    const float* Xb = (useH ? g_Hf : X) + ((size_t)b * NPIX + r0) * NC;
    for (int i = t; i < 4096; i += 256) { As[i] = Xb[i]; Ws[i] = W[i]; }
    __syncthreads();

    int tx = t & 15, ty = t >> 4;
    int c4 = tx * 4, r4 = ty * 4;
    float acc[4][4];
    #pragma unroll
    for (int i = 0; i < 4; i++)
        #pragma unroll
        for (int j = 0; j < 4; j++) acc[i][j] = 0.f;

    for (int k = 0; k < 64; k += 4) {
        float4 w0 = *(const float4*)&Ws[(k+0)*64 + c4];
        float4 w1 = *(const float4*)&Ws[(k+1)*64 + c4];
        float4 w2 = *(const float4*)&Ws[(k+2)*64 + c4];
        float4 w3 = *(const float4*)&Ws[(k+3)*64 + c4];
        #pragma unroll
        for (int i = 0; i < 4; i++) {
            float4 a = *(const float4*)&As[(r4+i)*64 + k];
            acc[i][0] += a.x*w0.x + a.y*w1.x + a.z*w2.x + a.w*w3.x;
            acc[i][1] += a.x*w0.y + a.y*w1.y + a.z*w2.y + a.w*w3.y;
            acc[i][2] += a.x*w0.z + a.y*w1.z + a.z*w2.z + a.w*w3.z;
            acc[i][3] += a.x*w0.w + a.y*w1.w + a.z*w2.w + a.w*w3.w;
        }
    }
    float4 bv = *(const float4*)&bias[c4];
    #pragma unroll
    for (int i = 0; i < 4; i++) {
        int r = r0 + r4 + i;
        float s = 0.1f * g_dv2[b*NPIX + r];          // fold invDE=0.1 here
        float4 o;
        o.x = (acc[i][0] + bv.x) * s;
        o.y = (acc[i][1] + bv.y) * s;
        o.z = (acc[i][2] + bv.z) * s;
        o.w = (acc[i][3] + bv.w) * s;
        *(float4*)&g_Z[((size_t)b*NPIX + r) * NC + c4] = o;
    }
}

// ---------------- K4/K7: hyperedge gather, float4: 16 threads/edge, 16 edges/block
__global__ void k_edge()
{
    int b = blockIdx.y, t = threadIdx.x;
    int e  = blockIdx.x * 16 + (t >> 4);
    int c4 = (t & 15) * 4;
    const int* __restrict__ tk = &g_topk[(b*NPIX + e) * TKPAD];
    int4 i0 = *(const int4*)tk;
    int4 i1 = *(const int4*)(tk + 4);
    int2 i2 = *(const int2*)(tk + 8);
    float4 acc;
    acc =            *(const float4*)&g_Z[((b*NPIX + i0.x) << 6) + c4];
    acc = f4add(acc, *(const float4*)&g_Z[((b*NPIX + i0.y) << 6) + c4]);
    acc = f4add(acc, *(const float4*)&g_Z[((b*NPIX + i0.z) << 6) + c4]);
    acc = f4add(acc, *(const float4*)&g_Z[((b*NPIX + i0.w) << 6) + c4]);
    acc = f4add(acc, *(const float4*)&g_Z[((b*NPIX + i1.x) << 6) + c4]);
    acc = f4add(acc, *(const float4*)&g_Z[((b*NPIX + i1.y) << 6) + c4]);
    acc = f4add(acc, *(const float4*)&g_Z[((b*NPIX + i1.z) << 6) + c4]);
    acc = f4add(acc, *(const float4*)&g_Z[((b*NPIX + i1.w) << 6) + c4]);
    acc = f4add(acc, *(const float4*)&g_Z[((b*NPIX + i2.x) << 6) + c4]);
    acc = f4add(acc, *(const float4*)&g_Z[((b*NPIX + i2.y) << 6) + c4]);
    *(float4*)&g_Y[((b*NPIX + e) << 6) + c4] = acc;
}

// ---------------- K5/K8: vertex gather: block per vertex, 16 slices x 16 threads float4
__global__ void k_vertex()
{
    int b = blockIdx.y, u = blockIdx.x, t = threadIdx.x;
    int c4 = (t & 15) * 4, s = t >> 4;                // slice 0..15
    __shared__ float4 red[256];
    int o0 = g_off[b*(NPIX+1) + u];
    int o1 = g_off[b*(NPIX+1) + u + 1];
    float4 acc = make_float4(0.f, 0.f, 0.f, 0.f);
    for (int p = o0 + s; p < o1; p += 16) {
        int e = g_ecol[b*NNZ + p];
        acc = f4add(acc, *(const float4*)&g_Y[((b*NPIX + e) << 6) + c4]);
    }
    red[t] = acc; __syncthreads();
    if (t < 128) red[t] = f4add(red[t], red[t+128]); __syncthreads();
    if (t < 64)  red[t] = f4add(red[t], red[t+64]);  __syncthreads();
    if (t < 32)  red[t] = f4add(red[t], red[t+32]);  __syncthreads();
    if (t < 16) {
        float4 tot = f4add(red[t], red[t+16]);
        float sc = g_dv2[b*NPIX + u];
        float4 o;
        o.x = fmaxf(tot.x * sc, 0.f);
        o.y = fmaxf(tot.y * sc, 0.f);
        o.z = fmaxf(tot.z * sc, 0.f);
        o.w = fmaxf(tot.w * sc, 0.f);
        *(float4*)&g_Hf[((b*NPIX + u) << 6) + t*4] = o;
    }
}

// ---------------- K9: final 1x1 conv + relu + per-batch sum, wide grid
__global__ void k_final(const float* __restrict__ wc,
                        const float* __restrict__ bc,
                        float* __restrict__ out)
{
    int b = blockIdx.y, t = threadIdx.x;
    __shared__ float ws[NC];
    __shared__ float red[256];
    if (t < NC) ws[t] = wc[t];
    __syncthreads();
    const float* hb = g_Hf + (size_t)b * NPIX * NC;   // viewed as (C, NPIX) via raw reshape
    int p = blockIdx.x * 256 + t;
    float lsum = 0.f;
    if (p < NPIX) {
        float acc = bc[0];
        #pragma unroll
        for (int c = 0; c < NC; c++) acc += hb[c*NPIX + p] * ws[c];
        lsum = fmaxf(acc, 0.f);
    }
    red[t] = lsum; __syncthreads();
    for (int s = 128; s > 0; s >>= 1) { if (t < s) red[t] += red[t+s]; __syncthreads(); }
    if (t == 0) atomicAdd(&out[b], red[0]);
}

// ---------------- launch ----------------
extern "C" void kernel_launch(void* const* d_in, const int* in_sizes, int n_in,
                              void* d_out, int out_size)
{
    const float* x      = (const float*)d_in[0];
    const float* w_con1 = (const float*)d_in[1];
    const float* b_con1 = (const float*)d_in[2];
    const float* W1     = (const float*)d_in[3];
    const float* b1     = (const float*)d_in[4];
    const float* W2     = (const float*)d_in[5];
    const float* b2     = (const float*)d_in[6];
    const float* w_con2 = (const float*)d_in[7];
    const float* b_con2 = (const float*)d_in[8];
    float* out = (float*)d_out;

    k_convA<<<dim3(7, NB), 256>>>(x, w_con1, b_con1);
    k_build<<<NB, 1024>>>(out);

    // layer 1
    k_gemm<<<dim3(NPIX / 64, NB), 256>>>(x, W1, b1, 0);
    k_edge<<<dim3(NPIX / 16, NB), 256>>>();
    k_vertex<<<dim3(NPIX, NB), 256>>>();

    // layer 2
    k_gemm<<<dim3(NPIX / 64, NB), 256>>>(nullptr, W2, b2, 1);
    k_edge<<<dim3(NPIX / 16, NB), 256>>>();
    k_vertex<<<dim3(NPIX, NB), 256>>>();

    k_final<<<dim3(7, NB), 256>>>(w_con2, b_con2, out);
}

// round 10
// speedup vs baseline: 1.1179x; 1.1179x over previous
#include <cuda_runtime.h>
#include <math.h>

#define NB    8
#define NC    64
#define NPIX  1600
#define TOPK  10
#define TKPAD 12
#define NNZ   (NPIX * TOPK)
#define SORTN 2048
#define FULLW 0xFFFFFFFFu

// ---------------- static scratch (no runtime allocation) ----------------
__device__ float g_xx  [NB * NPIX];        // relu conv logits (pre-softmax)
__device__ int   g_topk[NB * NPIX * TKPAD];
__device__ float g_dv2 [NB * NPIX];
__device__ int   g_off [NB * (NPIX + 1)];
__device__ int   g_ecol[NB * NNZ];
__device__ float g_Z   [NB * NPIX * NC];   // 0.1*dv2-scaled features (X@W + b)
__device__ float g_Y   [NB * NPIX * NC];   // per-hyperedge features
__device__ float g_Hf  [NB * NPIX * NC];   // vertex output of a layer

__device__ __forceinline__ float4 f4add(float4 a, float4 b) {
    a.x += b.x; a.y += b.y; a.z += b.z; a.w += b.w; return a;
}
__device__ __forceinline__ unsigned long long u64min_(unsigned long long a, unsigned long long b) { return a < b ? a : b; }
__device__ __forceinline__ unsigned long long u64max_(unsigned long long a, unsigned long long b) { return a > b ? a : b; }

// ---------------- K1: 1x1 conv + relu, wide grid (logits only)
__global__ void k_convA(const float* __restrict__ x,
                        const float* __restrict__ w,
                        const float* __restrict__ bconst)
{
    int b = blockIdx.y, t = threadIdx.x;
    __shared__ float ws[NC];
    if (t < NC) ws[t] = w[t];
    __syncthreads();
    int p = blockIdx.x * 256 + t;
    if (p >= NPIX) return;
    const float* xb = x + (size_t)b * NC * NPIX;
    float acc = bconst[0];
    #pragma unroll
    for (int c = 0; c < NC; c++) acc += xb[c*NPIX + p] * ws[c];
    g_xx[b*NPIX + p] = fmaxf(acc, 0.f);
}

// ---------------- K2: softmax + full graph build per batch.
__global__ __launch_bounds__(1024) void k_build(float* __restrict__ outz)
{
    int b = blockIdx.x, t = threadIdx.x;
    int lane = t & 31, wid = t >> 5;
    __shared__ unsigned long long skey[SORTN];      // 16 KB
    __shared__ unsigned short rs[NPIX], re[NPIX];   // run start/end per sorted pos
    __shared__ unsigned short pos[NPIX];            // original idx -> sorted pos
    __shared__ int dv[NPIX];                        // DV, later reused as fill cursor
    __shared__ int off[NPIX + 1];
    __shared__ int part[1024];                      // scan scratch / float scratch

    if (t == 0) outz[b] = 0.f;                      // zero the output accumulator

    // ---- softmax over relu logits (1600 elems, 1024 threads) ----
    float* rf = (float*)part;
    float v0 = g_xx[b*NPIX + t];
    float v1 = (t + 1024 < NPIX) ? g_xx[b*NPIX + t + 1024] : -3.4e38f;
    rf[t] = fmaxf(v0, v1); __syncthreads();
    for (int s = 512; s > 0; s >>= 1) { if (t < s) rf[t] = fmaxf(rf[t], rf[t+s]); __syncthreads(); }
    float mx = rf[0]; __syncthreads();
    float e0 = expf(v0 - mx);
    float e1 = (t + 1024 < NPIX) ? expf(v1 - mx) : 0.f;
    rf[t] = e0 + e1; __syncthreads();
    for (int s = 512; s > 0; s >>= 1) { if (t < s) rf[t] += rf[t+s]; __syncthreads(); }
    float inv = 1.f / rf[0]; __syncthreads();

    // pack keys in regs: (float bits of xx)<<32 | idx  (xx > 0 => bits monotone)
    unsigned long long a0 = ((unsigned long long)__float_as_uint(e0 * inv) << 32) | (unsigned)t;
    unsigned long long a1 = (t + 1024 < NPIX)
        ? (((unsigned long long)__float_as_uint(e1 * inv) << 32) | (unsigned)(t + 1024))
        : 0xFFFFFFFFFFFFFFFFull;

    // reg-phase: exchange at distance j (<=16, intra-warp) for elements t, t+1024
    #define REGPHASE(KSZ, J) { \
        unsigned long long p0 = __shfl_xor_sync(FULLW, a0, (J)); \
        unsigned long long p1 = __shfl_xor_sync(FULLW, a1, (J)); \
        int i0 = t, i1 = t + 1024; \
        bool m0 = (((i0 & (J)) == 0) == ((i0 & (KSZ)) == 0)); \
        bool m1 = (((i1 & (J)) == 0) == ((i1 & (KSZ)) == 0)); \
        a0 = m0 ? u64min_(a0, p0) : u64max_(a0, p0); \
        a1 = m1 ? u64min_(a1, p1) : u64max_(a1, p1); }

    for (int ksz = 2; ksz <= 32; ksz <<= 1)
        for (int j = ksz >> 1; j >= 1; j >>= 1)
            REGPHASE(ksz, j);
    skey[t] = a0; skey[t + 1024] = a1; __syncthreads();

    for (int ksz = 64; ksz <= SORTN; ksz <<= 1) {
        int jstart = ksz >> 1;
        if (ksz == SORTN) {
            unsigned long long lo = u64min_(a0, a1), hi = u64max_(a0, a1);
            a0 = lo; a1 = hi;
            skey[t] = a0; skey[t + 1024] = a1; __syncthreads();
            jstart = 512;
        }
        for (int j = jstart; j >= 32; j >>= 1) {
            #pragma unroll
            for (int r = 0; r < 2; r++) {
                int i = t + r * 1024;
                int ixj = i ^ j;
                if (ixj > i) {
                    unsigned long long a = skey[i], c = skey[ixj];
                    bool up = ((i & ksz) == 0);
                    if ((a > c) == up) { skey[i] = c; skey[ixj] = a; }
                }
            }
            __syncthreads();
        }
        a0 = skey[t]; a1 = skey[t + 1024];
        for (int j = 16; j >= 1; j >>= 1)
            REGPHASE(ksz, j);
        skey[t] = a0; skey[t + 1024] = a1; __syncthreads();
    }

    // run bounds (equal-value runs) via binary search; pos scatter; DV=0
    for (int p = t; p < NPIX; p += 1024) {
        unsigned v = (unsigned)(skey[p] >> 32);
        int lo = 0, hi = p;
        while (lo < hi) { int m = (lo + hi) >> 1;
            if ((unsigned)(skey[m] >> 32) < v) lo = m + 1; else hi = m; }
        rs[p] = (unsigned short)lo;
        int lo2 = p + 1, hi2 = NPIX;
        while (lo2 < hi2) { int m = (lo2 + hi2) >> 1;
            if ((unsigned)(skey[m] >> 32) <= v) lo2 = m + 1; else hi2 = m; }
        re[p] = (unsigned short)(lo2 - 1);
        pos[(unsigned)(skey[p] & 0xFFFFFFFFu)] = (unsigned short)p;
        dv[p] = 0;
    }
    __syncthreads();

    // per-row top-k walk (exact stable-argsort (d,idx) semantics incl. ties)
    for (int i = t; i < NPIX; i += 1024) {
        int p = pos[i];
        float vi = __uint_as_float((unsigned)(skey[p] >> 32));
        int out[TOPK]; int cnt = 0;
        int a = rs[p], bnd = re[p];
        for (int q = a; q <= bnd && cnt < TOPK; q++)
            out[cnt++] = (int)(skey[q] & 0xFFFFFFFFu);
        int L = a - 1, R = bnd + 1;
        while (cnt < TOPK) {
            float dL = (L >= 0)   ? vi - __uint_as_float((unsigned)(skey[L] >> 32)) : 3.4e38f;
            float dR = (R < NPIX) ? __uint_as_float((unsigned)(skey[R] >> 32)) - vi : 3.4e38f;
            if (dL < dR) {
                int s2 = rs[L];
                for (int q = s2; q <= L && cnt < TOPK; q++)
                    out[cnt++] = (int)(skey[q] & 0xFFFFFFFFu);
                L = s2 - 1;
            } else if (dR < dL) {
                int e2 = re[R];
                for (int q = R; q <= e2 && cnt < TOPK; q++)
                    out[cnt++] = (int)(skey[q] & 0xFFFFFFFFu);
                R = e2 + 1;
            } else {                                  // exact distance tie: merge by idx
                int sL = rs[L], eR = re[R];
                int qa = sL, qb = R;
                while (cnt < TOPK && (qa <= L || qb <= eR)) {
                    int ia = (qa <= L)  ? (int)(skey[qa] & 0xFFFFFFFFu) : 0x7FFFFFFF;
                    int ib = (qb <= eR) ? (int)(skey[qb] & 0xFFFFFFFFu) : 0x7FFFFFFF;
                    if (ia < ib) { out[cnt++] = ia; qa++; }
                    else         { out[cnt++] = ib; qb++; }
                }
                L = sL - 1; R = eR + 1;
            }
        }
        bool has = false;
        #pragma unroll
        for (int j2 = 0; j2 < TOPK; j2++) has |= (out[j2] == i);
        if (!has) out[TOPK-1] = i;                    // reference self rule

        int base = (b*NPIX + i) * TKPAD;
        #pragma unroll
        for (int j2 = 0; j2 < TOPK; j2++) {
            g_topk[base + j2] = out[j2];
            atomicAdd(&dv[out[j2]], 1);
        }
    }
    __syncthreads();

    // exclusive scan of DV (pairs) -> offsets; dv2   [shfl 3-level scan, 3 barriers]
    int p0 = t * 2;
    int sv = (p0 < NPIX) ? dv[p0] + dv[p0+1] : 0;
    int incl = sv;
    #pragma unroll
    for (int d2 = 1; d2 < 32; d2 <<= 1) {
        int vv = __shfl_up_sync(FULLW, incl, d2);
        if (lane >= d2) incl += vv;
    }
    if (lane == 31) part[wid] = incl;
    __syncthreads();
    if (wid == 0) {
        int w = part[lane];
        #pragma unroll
        for (int d2 = 1; d2 < 32; d2 <<= 1) {
            int vv = __shfl_up_sync(FULLW, w, d2);
            if (lane >= d2) w += vv;
        }
        part[lane] = w;
    }
    __syncthreads();
    int total_incl = incl + (wid ? part[wid-1] : 0);
    if (p0 < NPIX) {
        int excl = total_incl - sv;
        off[p0] = excl; off[p0+1] = excl + dv[p0];
        g_off[b*(NPIX+1) + p0]     = excl;
        g_off[b*(NPIX+1) + p0 + 1] = excl + dv[p0];
        g_dv2[b*NPIX + p0]     = rsqrtf((float)dv[p0]);
        g_dv2[b*NPIX + p0 + 1] = rsqrtf((float)dv[p0+1]);
    }
    if (t == 0) { off[NPIX] = NNZ; g_off[b*(NPIX+1) + NPIX] = NNZ; }
    __syncthreads();

    // CSR fill (reuse dv as cursor), plain atomics (R9 aggregation regressed)
    for (int p = t; p < NPIX; p += 1024) dv[p] = 0;
    __syncthreads();
    for (int s2 = t; s2 < NNZ; s2 += 1024) {
        int e = s2 / TOPK, j2 = s2 - e * TOPK;
        int v = g_topk[(b*NPIX + e) * TKPAD + j2];
        int ppos = atomicAdd(&dv[v], 1);
        g_ecol[b*NNZ + off[v] + ppos] = e;
    }
}

// ---------------- K3/K6: Z[v,:] = 0.1*dv2[v] * (X[v,:] @ W + bias)
__global__ void k_gemm(const float* __restrict__ X,
                       const float* __restrict__ W,
                       const float* __restrict__ bias,
                       int useH)
{
    int b  = blockIdx.y;
    int r0 = blockIdx.x * 64;
    __shared__ float As[64 * 64];
    __shared__ float Ws[64 * 64];
    int t = threadIdx.x;
    const float* Xb = (useH ? g_Hf : X) + ((size_t)b * NPIX + r0) * NC;
    for (int i = t; i < 4096; i += 256) { As[i] = Xb[i]; Ws[i] = W[i]; }
    __syncthreads();

    int tx = t & 15, ty = t >> 4;
    int c4 = tx * 4, r4 = ty * 4;
    float acc[4][4];
    #pragma unroll
    for (int i = 0; i < 4; i++)
        #pragma unroll
        for (int j = 0; j < 4; j++) acc[i][j] = 0.f;

    for (int k = 0; k < 64; k += 4) {
        float4 w0 = *(const float4*)&Ws[(k+0)*64 + c4];
        float4 w1 = *(const float4*)&Ws[(k+1)*64 + c4];
        float4 w2 = *(const float4*)&Ws[(k+2)*64 + c4];
        float4 w3 = *(const float4*)&Ws[(k+3)*64 + c4];
        #pragma unroll
        for (int i = 0; i < 4; i++) {
            float4 a = *(const float4*)&As[(r4+i)*64 + k];
            acc[i][0] += a.x*w0.x + a.y*w1.x + a.z*w2.x + a.w*w3.x;
            acc[i][1] += a.x*w0.y + a.y*w1.y + a.z*w2.y + a.w*w3.y;
            acc[i][2] += a.x*w0.z + a.y*w1.z + a.z*w2.z + a.w*w3.z;
            acc[i][3] += a.x*w0.w + a.y*w1.w + a.z*w2.w + a.w*w3.w;
        }
    }
    float4 bv = *(const float4*)&bias[c4];
    #pragma unroll
    for (int i = 0; i < 4; i++) {
        int r = r0 + r4 + i;
        float s = 0.1f * g_dv2[b*NPIX + r];          // fold invDE=0.1 here
        float4 o;
        o.x = (acc[i][0] + bv.x) * s;
        o.y = (acc[i][1] + bv.y) * s;
        o.z = (acc[i][2] + bv.z) * s;
        o.w = (acc[i][3] + bv.w) * s;
        *(float4*)&g_Z[((size_t)b*NPIX + r) * NC + c4] = o;
    }
}

// ---------------- K4/K7: hyperedge gather, float4: 16 threads/edge, 16 edges/block
__global__ void k_edge()
{
    int b = blockIdx.y, t = threadIdx.x;
    int e  = blockIdx.x * 16 + (t >> 4);
    int c4 = (t & 15) * 4;
    const int* __restrict__ tk = &g_topk[(b*NPIX + e) * TKPAD];
    int4 i0 = *(const int4*)tk;
    int4 i1 = *(const int4*)(tk + 4);
    int2 i2 = *(const int2*)(tk + 8);
    float4 acc;
    acc =            *(const float4*)&g_Z[((b*NPIX + i0.x) << 6) + c4];
    acc = f4add(acc, *(const float4*)&g_Z[((b*NPIX + i0.y) << 6) + c4]);
    acc = f4add(acc, *(const float4*)&g_Z[((b*NPIX + i0.z) << 6) + c4]);
    acc = f4add(acc, *(const float4*)&g_Z[((b*NPIX + i0.w) << 6) + c4]);
    acc = f4add(acc, *(const float4*)&g_Z[((b*NPIX + i1.x) << 6) + c4]);
    acc = f4add(acc, *(const float4*)&g_Z[((b*NPIX + i1.y) << 6) + c4]);
    acc = f4add(acc, *(const float4*)&g_Z[((b*NPIX + i1.z) << 6) + c4]);
    acc = f4add(acc, *(const float4*)&g_Z[((b*NPIX + i1.w) << 6) + c4]);
    acc = f4add(acc, *(const float4*)&g_Z[((b*NPIX + i2.x) << 6) + c4]);
    acc = f4add(acc, *(const float4*)&g_Z[((b*NPIX + i2.y) << 6) + c4]);
    *(float4*)&g_Y[((b*NPIX + e) << 6) + c4] = acc;
}

// ---------------- K5/K8: vertex gather: block per vertex, 16 slices x 16 threads float4
__global__ void k_vertex()
{
    int b = blockIdx.y, u = blockIdx.x, t = threadIdx.x;
    int c4 = (t & 15) * 4, s = t >> 4;                // slice 0..15
    __shared__ float4 red[256];
    int o0 = g_off[b*(NPIX+1) + u];
    int o1 = g_off[b*(NPIX+1) + u + 1];
    float4 acc = make_float4(0.f, 0.f, 0.f, 0.f);
    for (int p = o0 + s; p < o1; p += 16) {
        int e = g_ecol[b*NNZ + p];
        acc = f4add(acc, *(const float4*)&g_Y[((b*NPIX + e) << 6) + c4]);
    }
    red[t] = acc; __syncthreads();
    if (t < 128) red[t] = f4add(red[t], red[t+128]); __syncthreads();
    if (t < 64)  red[t] = f4add(red[t], red[t+64]);  __syncthreads();
    if (t < 32)  red[t] = f4add(red[t], red[t+32]);  __syncthreads();
    if (t < 16) {
        float4 tot = f4add(red[t], red[t+16]);
        float sc = g_dv2[b*NPIX + u];
        float4 o;
        o.x = fmaxf(tot.x * sc, 0.f);
        o.y = fmaxf(tot.y * sc, 0.f);
        o.z = fmaxf(tot.z * sc, 0.f);
        o.w = fmaxf(tot.w * sc, 0.f);
        *(float4*)&g_Hf[((b*NPIX + u) << 6) + t*4] = o;
    }
}

// ---------------- K9: final 1x1 conv + relu + per-batch sum, wide grid
__global__ void k_final(const float* __restrict__ wc,
                        const float* __restrict__ bc,
                        float* __restrict__ out)
{
    int b = blockIdx.y, t = threadIdx.x;
    __shared__ float ws[NC];
    __shared__ float red[256];
    if (t < NC) ws[t] = wc[t];
    __syncthreads();
    const float* hb = g_Hf + (size_t)b * NPIX * NC;   // viewed as (C, NPIX) via raw reshape
    int p = blockIdx.x * 256 + t;
    float lsum = 0.f;
    if (p < NPIX) {
        float acc = bc[0];
        #pragma unroll
        for (int c = 0; c < NC; c++) acc += hb[c*NPIX + p] * ws[c];
        lsum = fmaxf(acc, 0.f);
    }
    red[t] = lsum; __syncthreads();
    for (int s = 128; s > 0; s >>= 1) { if (t < s) red[t] += red[t+s]; __syncthreads(); }
    if (t == 0) atomicAdd(&out[b], red[0]);
}

// ---------------- launch ----------------
extern "C" void kernel_launch(void* const* d_in, const int* in_sizes, int n_in,
                              void* d_out, int out_size)
{
    const float* x      = (const float*)d_in[0];
    const float* w_con1 = (const float*)d_in[1];
    const float* b_con1 = (const float*)d_in[2];
    const float* W1     = (const float*)d_in[3];
    const float* b1     = (const float*)d_in[4];
    const float* W2     = (const float*)d_in[5];
    const float* b2     = (const float*)d_in[6];
    const float* w_con2 = (const float*)d_in[7];
    const float* b_con2 = (const float*)d_in[8];
    float* out = (float*)d_out;

    k_convA<<<dim3(7, NB), 256>>>(x, w_con1, b_con1);
    k_build<<<NB, 1024>>>(out);

    // layer 1
    k_gemm<<<dim3(NPIX / 64, NB), 256>>>(x, W1, b1, 0);
    k_edge<<<dim3(NPIX / 16, NB), 256>>>();
    k_vertex<<<dim3(NPIX, NB), 256>>>();

    // layer 2
    k_gemm<<<dim3(NPIX / 64, NB), 256>>>(nullptr, W2, b2, 1);
    k_edge<<<dim3(NPIX / 16, NB), 256>>>();
    k_vertex<<<dim3(NPIX, NB), 256>>>();

    k_final<<<dim3(7, NB), 256>>>(w_con2, b_con2, out);
}